// round 16
// baseline (speedup 1.0000x reference)
#include <cuda_runtime.h>
#include <cuda_fp16.h>
#include <cstdint>
#include <math.h>

// Problem constants
#define BB   1024
#define LL   2048
#define DEC  64
#define HH   128
#define GG   512         // 4*H gate rows
#define NKT  9           // k-tiles of 16: k 0..15 emb, 16..143 h (no padding)
#define BT   8           // batch rows per CTA (= mma N)
#define NCTA (BB/BT)     // 128
#define NTHR 512         // 16 warps -> 4 per SMSP
#define NW   16
#define XST  200         // xhT row stride in fp16
#define FPW  18          // W fragments per warp: 2 mtiles x 9 ktiles
#define NFRAG (NW * FPW * 32)   // 9216

// ---------------- persistent device scratch ----------------
__device__ uint4  g_Whf_e[NFRAG];                 // enc W fp16 frags (i/f/o pre-scaled 0.5)
__device__ uint4  g_Whf_d[NFRAG];                 // dec
__device__ __half g_femb[(size_t)BB * LL * 16];   // encoder embedding features
__device__ float2 g_fs[(size_t)BB * LL];          // encoder (cont*w, X) scalars
__device__ __half g_demb[BB * DEC * 16];          // decoder embeddings
__device__ float  g_ds[BB * DEC];                 // decoder cont*w scalars

// ---------------- smem byte layout ----------------
#define XH0_OFF   0                         // 3200 B : xh^T fp16 [8][200] buf 0
#define XH1_OFF   3200                      // 3200 B : buf 1
#define HBUF_OFF  6400                      // 4096 B : h fp32 [128][8] (decoder)
#define HW_OFF    10496                     // 3096 B : head weights/biases
#define SBUF_OFF  13592                     // 128 B  : (cont*w, X) float2 [2][8]
#define SMEM_TOTAL 13720

// ---------------- mma wrapper ----------------
__device__ __forceinline__ void mma_f16(float* d, const uint4& a,
                                        uint32_t b0, uint32_t b1) {
    asm volatile(
        "mma.sync.aligned.m16n8k16.row.col.f32.f16.f16.f32 "
        "{%0,%1,%2,%3}, {%4,%5,%6,%7}, {%8,%9}, {%0,%1,%2,%3};"
        : "+f"(d[0]), "+f"(d[1]), "+f"(d[2]), "+f"(d[3])
        : "r"(a.x), "r"(a.y), "r"(a.z), "r"(a.w), "r"(b0), "r"(b1));
}

// ---------------- fast activations (HW tanh, fp32) ----------------
__device__ __forceinline__ float th(float x) {
    float y;
    asm("tanh.approx.f32 %0, %1;" : "=f"(y) : "f"(x));
    return y;
}
// input pre-scaled by 0.5 via weights/bias: sigmoid(2x) = .5*th(x)+.5
__device__ __forceinline__ float sgp(float xh) {
    return fmaf(0.5f, th(xh), 0.5f);
}

// ---------------- merged prep (single launch keeps ncu on model_kernel) ------
__device__ __forceinline__ float getW(const float* Wih, const float* Whh,
                                      int R, int k) {
    // new K space: k 0..15 = emb cols of Wih; 16..143 = Whh
    if (k < 16) return Wih[R * 18 + k];
    return Whh[R * 128 + (k - 16)];
}
__device__ __forceinline__ uint32_t packh2(float a, float b) {
    __half2 h = __floats2half2_rn(a, b);   // low = a
    return *reinterpret_cast<uint32_t*>(&h);
}

#define WBLK   (NFRAG / 256)                             // 36
#define FEMBLK ((int)(((size_t)BB * LL * 16) / 256))     // 131072
#define FSBLK  ((int)(((size_t)BB * LL) / 256))          // 8192
#define FDEBLK ((BB * DEC * 16) / 256)                   // 4096
#define FDSBLK ((BB * DEC) / 256)                        // 256
#define PREP_GRID (2 * WBLK + FEMBLK + FSBLK + FDEBLK + FDSBLK)

__device__ void prep_W_one(const float* __restrict__ Wih,
                           const float* __restrict__ Whh,
                           uint4* __restrict__ w_out, int idx) {
    int frag = idx >> 5, lane = idx & 31;
    int w = frag / FPW, rem = frag - w * FPW;
    int mt = rem / NKT, kt = rem - mt * NKT;
    int g = lane >> 2, t4 = lane & 3;
    int e = w * 8 + g;
    int R0 = (2 * mt + 0) * 128 + e;   // s=0
    int R1 = (2 * mt + 1) * 128 + e;   // s=1
    float s0 = (mt == 1) ? 1.0f : 0.5f;   // gate g unscaled; i scaled
    float s1 = 0.5f;                      // f and o scaled
    int kc = kt * 16 + 2 * t4;
    float v[8];
    v[0] = s0 * getW(Wih, Whh, R0, kc);     v[1] = s0 * getW(Wih, Whh, R0, kc + 1);
    v[2] = s1 * getW(Wih, Whh, R1, kc);     v[3] = s1 * getW(Wih, Whh, R1, kc + 1);
    v[4] = s0 * getW(Wih, Whh, R0, kc + 8); v[5] = s0 * getW(Wih, Whh, R0, kc + 9);
    v[6] = s1 * getW(Wih, Whh, R1, kc + 8); v[7] = s1 * getW(Wih, Whh, R1, kc + 9);
    w_out[idx] = make_uint4(packh2(v[0], v[1]), packh2(v[2], v[3]),
                            packh2(v[4], v[5]), packh2(v[6], v[7]));
}

__global__ void prep_all(const float* __restrict__ Wih_e, const float* __restrict__ Whh_e,
                         const float* __restrict__ Wih_d, const float* __restrict__ Whh_d,
                         const int* __restrict__ cat_in, const float* __restrict__ cont_in,
                         const float* __restrict__ X_in,
                         const int* __restrict__ cat_out, const float* __restrict__ cont_out,
                         const float* __restrict__ emb, const float* __restrict__ cw) {
    int blk = blockIdx.x;
    if (blk < WBLK) {
        prep_W_one(Wih_e, Whh_e, g_Whf_e, blk * 256 + threadIdx.x);
    } else if (blk < 2 * WBLK) {
        prep_W_one(Wih_d, Whh_d, g_Whf_d, (blk - WBLK) * 256 + threadIdx.x);
    } else if (blk < 2 * WBLK + FEMBLK) {
        size_t idx = (size_t)(blk - 2 * WBLK) * 256 + threadIdx.x;
        size_t bl = idx >> 4;
        int j = (int)(idx & 15);
        g_femb[idx] = __float2half(emb[cat_in[bl] * 16 + j]);
    } else if (blk < 2 * WBLK + FEMBLK + FSBLK) {
        size_t bl = (size_t)(blk - 2 * WBLK - FEMBLK) * 256 + threadIdx.x;
        g_fs[bl] = make_float2(cont_in[bl] * cw[0], X_in[bl]);
    } else if (blk < 2 * WBLK + FEMBLK + FSBLK + FDEBLK) {
        int idx = (blk - 2 * WBLK - FEMBLK - FSBLK) * 256 + threadIdx.x;
        int bl = idx >> 4, j = idx & 15;
        g_demb[idx] = __float2half(emb[cat_out[bl] * 16 + j]);
    } else {
        int bl = (blk - 2 * WBLK - FEMBLK - FSBLK - FDEBLK) * 256 + threadIdx.x;
        g_ds[bl] = cont_out[bl] * cw[0];
    }
}

// ---------------- main persistent kernel ----------------
__global__ void __launch_bounds__(NTHR, 1)
model_kernel(const float* __restrict__ b_e, const float* __restrict__ b_d,
             const float* __restrict__ Wih_e, const float* __restrict__ Wih_d,
             const float* __restrict__ Wm, const float* __restrict__ bm,
             const float* __restrict__ Wsw, const float* __restrict__ bs,
             const float* __restrict__ Wv, const float* __restrict__ bv,
             float* __restrict__ out) {
    extern __shared__ char smem[];
    __half* xbuf[2] = { reinterpret_cast<__half*>(smem + XH0_OFF),
                        reinterpret_cast<__half*>(smem + XH1_OFF) };
    float*  hbuf = reinterpret_cast<float*>(smem + HBUF_OFF);
    float*  hw   = reinterpret_cast<float*>(smem + HW_OFF);
    float2* sbuf = reinterpret_cast<float2*>(smem + SBUF_OFF);   // [2][8]

    const int tid = threadIdx.x;
    const int b0r = blockIdx.x * BT;
    const int w = tid >> 5, lane = tid & 31;
    const int g = lane >> 2, t4 = lane & 3;
    const int e  = w * 8 + g;             // this thread's cell element
    const int c0 = 2 * t4;                // this thread's 2 batch cols

    // ---- load encoder W into registers (18 frags = 72 regs) ----
    uint4 Wh[FPW];
    {
        const uint4* src = g_Whf_e + (size_t)w * FPW * 32 + lane;
#pragma unroll
        for (int i = 0; i < FPW; ++i) Wh[i] = src[i * 32];
    }
    // biases + rank-1 feature weights (cont col 16, X col 17), i/f/o scaled 0.5
    float bi, bf, bg, bo, wci, wxi, wcf, wxf, wcg, wxg, wco, wxo;
    {
        bi = 0.5f * b_e[e];        bf = 0.5f * b_e[128 + e];
        bg = b_e[256 + e];         bo = 0.5f * b_e[384 + e];
        wci = 0.5f * Wih_e[(0 * 128 + e) * 18 + 16];
        wxi = 0.5f * Wih_e[(0 * 128 + e) * 18 + 17];
        wcf = 0.5f * Wih_e[(1 * 128 + e) * 18 + 16];
        wxf = 0.5f * Wih_e[(1 * 128 + e) * 18 + 17];
        wcg =        Wih_e[(2 * 128 + e) * 18 + 16];
        wxg =        Wih_e[(2 * 128 + e) * 18 + 17];
        wco = 0.5f * Wih_e[(3 * 128 + e) * 18 + 16];
        wxo = 0.5f * Wih_e[(3 * 128 + e) * 18 + 17];
    }

    // zero both xh buffers (h0 = 0)
    for (int i = tid; i < (2 * BT * XST) / 2; i += NTHR)
        reinterpret_cast<uint32_t*>(xbuf[0])[i] = 0;

    // head weights
    if (tid < 128) {
        hw[tid]       = Wm[tid];
        hw[128 + tid] = Wsw[tid];
#pragma unroll
        for (int d = 0; d < 4; ++d) hw[256 + d * 128 + tid] = Wv[d * 128 + tid];
    }
    if (tid == 0) {
        hw[768] = bm[0]; hw[769] = bs[0];
        hw[770] = bv[0]; hw[771] = bv[1]; hw[772] = bv[2]; hw[773] = bv[3];
    }
    __syncthreads();
    // initial features (t=0) -> buffer 0
    if (tid < BT * 16) {
        int pr = tid >> 4, pk = tid & 15;
        xbuf[0][pr * XST + pk] = g_femb[(size_t)(b0r + pr) * (LL * 16) + pk];
    } else if (tid < BT * 16 + BT) {
        int r = tid - BT * 16;
        sbuf[r] = g_fs[(size_t)(b0r + r) * LL];
    }

    float c[2] = {0.f, 0.f};   // states: (e,c0), (e,c0+1)

#pragma unroll 1
    for (int t = 0; t < LL + DEC; ++t) {
        if (t == LL) {
            const uint4* src = g_Whf_d + (size_t)w * FPW * 32 + lane;
#pragma unroll
            for (int i = 0; i < FPW; ++i) Wh[i] = src[i * 32];
            bi = 0.5f * b_d[e];        bf = 0.5f * b_d[128 + e];
            bg = b_d[256 + e];         bo = 0.5f * b_d[384 + e];
            wci = 0.5f * Wih_d[(0 * 128 + e) * 18 + 16];
            wxi = 0.5f * Wih_d[(0 * 128 + e) * 18 + 17];
            wcf = 0.5f * Wih_d[(1 * 128 + e) * 18 + 16];
            wxf = 0.5f * Wih_d[(1 * 128 + e) * 18 + 17];
            wcg =        Wih_d[(2 * 128 + e) * 18 + 16];
            wxg =        Wih_d[(2 * 128 + e) * 18 + 17];
            wco = 0.5f * Wih_d[(3 * 128 + e) * 18 + 16];
            wxo = 0.5f * Wih_d[(3 * 128 + e) * 18 + 17];
        }
        const __half* cur = xbuf[t & 1];
        __half*       nxt = xbuf[(t + 1) & 1];
        float2* sc = sbuf + (t & 1) * 8;
        float2* sn = sbuf + ((t + 1) & 1) * 8;
        __syncthreads();                      // cur + sc complete

        // ---- ISSUE feature prefetch LDG early; MMA phase hides its latency ----
        __half pe = __float2half(0.0f); float2 ps = make_float2(0.f, 0.f);
        float  pds = 0.0f;
        int pmode = 0, pr = 0, pk = 0;        // 1=enc emb, 2=enc scal, 3=dec emb, 4=dec scal
        if (t < LL - 1) {
            if (tid < 128) {
                pmode = 1; pr = tid >> 4; pk = tid & 15;
                pe = g_femb[(size_t)(b0r + pr) * (LL * 16) + (size_t)(t + 1) * 16 + pk];
            } else if (tid < 136) {
                pmode = 2; pr = tid - 128;
                ps = g_fs[(size_t)(b0r + pr) * LL + (t + 1)];
            }
        } else if (t >= LL && t < LL + DEC - 1) {
            int td = t - LL;
            if (tid < 128) {
                pmode = 3; pr = tid >> 4; pk = tid & 15;
                pe = g_demb[((b0r + pr) * DEC + td) * 16 + pk];
            } else if (tid < 136) {
                pmode = 4; pr = tid - 128;
                pds = g_ds[(b0r + pr) * DEC + td];
            }
        }

        // ---- scalar feature contribution (rank-2) folded into accumulator init ----
        float2 s0 = sc[c0], s1 = sc[c0 + 1];
        float dA[4], dB[4];                   // dA = {i,f}, dB = {g,o}
        dA[0] = fmaf(wxi, s0.y, fmaf(wci, s0.x, bi));
        dA[1] = fmaf(wxi, s1.y, fmaf(wci, s1.x, bi));
        dA[2] = fmaf(wxf, s0.y, fmaf(wcf, s0.x, bf));
        dA[3] = fmaf(wxf, s1.y, fmaf(wcf, s1.x, bf));
        dB[0] = fmaf(wxg, s0.y, fmaf(wcg, s0.x, bg));
        dB[1] = fmaf(wxg, s1.y, fmaf(wcg, s1.x, bg));
        dB[2] = fmaf(wxo, s0.y, fmaf(wco, s0.x, bo));
        dB[3] = fmaf(wxo, s1.y, fmaf(wco, s1.x, bo));

        // ---- gate GEMM: 9 k-tiles, no padding ----
        const __half* xp = cur + g * XST;
#pragma unroll
        for (int kt = 0; kt < NKT; ++kt) {
            uint32_t b0 = *reinterpret_cast<const uint32_t*>(xp + kt * 16 + 2 * t4);
            uint32_t b1 = *reinterpret_cast<const uint32_t*>(xp + kt * 16 + 2 * t4 + 8);
            mma_f16(dA, Wh[kt],       b0, b1);
            mma_f16(dB, Wh[NKT + kt], b0, b1);
        }

        // ---- LSTM cell: fully in registers, fp32 (2 states/thread) ----
        c[0] = sgp(dA[2]) * c[0] + sgp(dA[0]) * th(dB[0]);
        c[1] = sgp(dA[3]) * c[1] + sgp(dA[1]) * th(dB[1]);
        float h0 = sgp(dB[2]) * th(c[0]);
        float h1 = sgp(dB[3]) * th(c[1]);
        nxt[c0 * XST + 16 + e]       = __float2half(h0);
        nxt[(c0 + 1) * XST + 16 + e] = __float2half(h1);

        // ---- store prefetched features / seam copy ----
        if (pmode == 1 || pmode == 3) {
            nxt[pr * XST + pk] = pe;
        } else if (pmode == 2) {
            sn[pr] = ps;
        } else if (pmode == 4) {
            sn[pr].x = pds;                   // X part (.y) written by heads (mu)
        } else if (t == LL - 1) {
            // decoder t0 reuses encoder's last features
            if (tid < 128) {
                int qr = tid >> 4, qk = tid & 15;
                nxt[qr * XST + qk] = cur[qr * XST + qk];
            } else if (tid < 136) {
                sn[tid - 128] = sc[tid - 128];
            }
        }

        // ---- decoder heads ----
        if (t >= LL) {
            int td = t - LL;
            *reinterpret_cast<float2*>(hbuf + e * BT + c0) = make_float2(h0, h1);
            __syncthreads();                  // h complete for heads
            if (w < 8) {
                int r = w;                    // warps 0-7 -> 8 batch rows
                float hm = 0.f, hs = 0.f, hv0 = 0.f, hv1 = 0.f, hv2 = 0.f, hv3 = 0.f;
#pragma unroll
                for (int q4 = 0; q4 < 4; ++q4) {
                    int jj = lane + q4 * 32;
                    float hh = hbuf[jj * BT + r];
                    hm  = fmaf(hh, hw[jj], hm);
                    hs  = fmaf(hh, hw[128 + jj], hs);
                    hv0 = fmaf(hh, hw[256 + jj], hv0);
                    hv1 = fmaf(hh, hw[384 + jj], hv1);
                    hv2 = fmaf(hh, hw[512 + jj], hv2);
                    hv3 = fmaf(hh, hw[640 + jj], hv3);
                }
#pragma unroll
                for (int off = 16; off; off >>= 1) {
                    hm  += __shfl_xor_sync(0xffffffffu, hm,  off);
                    hs  += __shfl_xor_sync(0xffffffffu, hs,  off);
                    hv0 += __shfl_xor_sync(0xffffffffu, hv0, off);
                    hv1 += __shfl_xor_sync(0xffffffffu, hv1, off);
                    hv2 += __shfl_xor_sync(0xffffffffu, hv2, off);
                    hv3 += __shfl_xor_sync(0xffffffffu, hv3, off);
                }
                if (lane == 0) {
                    float mu = hm + hw[768];
                    float sp = hs + hw[769];
                    float stdv = fmaxf(sp, 0.0f) + log1pf(__expf(-fabsf(sp)));
                    int b = b0r + r;
                    out[b * DEC + td] = mu;
                    out[BB * DEC + b * DEC + td] = stdv;
                    float* vo = out + 2 * BB * DEC + (b * DEC + td) * 4;
                    vo[0] = hv0 + hw[770]; vo[1] = hv1 + hw[771];
                    vo[2] = hv2 + hw[772]; vo[3] = hv3 + hw[773];
                    sn[r].y = mu;             // mu feedback -> x_prev (fp32 exact)
                }
            }
        }
    }
}

// ---------------- launch ----------------
extern "C" void kernel_launch(void* const* d_in, const int* in_sizes, int n_in,
                              void* d_out, int out_size) {
    const int*   cat_in   = (const int*)d_in[0];
    const float* cont_in  = (const float*)d_in[1];
    const float* X_in     = (const float*)d_in[2];
    const int*   cat_out  = (const int*)d_in[3];
    const float* cont_out = (const float*)d_in[4];
    const float* emb      = (const float*)d_in[5];
    const float* cw       = (const float*)d_in[6];
    const float* Wih_e    = (const float*)d_in[7];
    const float* Whh_e    = (const float*)d_in[8];
    const float* b_e      = (const float*)d_in[9];
    const float* Wih_d    = (const float*)d_in[10];
    const float* Whh_d    = (const float*)d_in[11];
    const float* b_d      = (const float*)d_in[12];
    const float* Wm       = (const float*)d_in[13];
    const float* bm       = (const float*)d_in[14];
    const float* Ws       = (const float*)d_in[15];
    const float* bs       = (const float*)d_in[16];
    const float* Wv       = (const float*)d_in[17];
    const float* bv       = (const float*)d_in[18];
    float* out = (float*)d_out;

    prep_all<<<PREP_GRID, 256>>>(Wih_e, Whh_e, Wih_d, Whh_d,
                                 cat_in, cont_in, X_in, cat_out, cont_out,
                                 emb, cw);

    cudaFuncSetAttribute(model_kernel, cudaFuncAttributeMaxDynamicSharedMemorySize,
                         SMEM_TOTAL);
    model_kernel<<<NCTA, NTHR, SMEM_TOTAL>>>(b_e, b_d, Wih_e, Wih_d,
                                             Wm, bm, Ws, bs, Wv, bv, out);
}